// round 10
// baseline (speedup 1.0000x reference)
#include <cuda_runtime.h>

#define TT 512
#define BTILE 16
#define NTHREADS 768

typedef unsigned long long ull;

struct Smem {
    float w0[64 * 256];    // [k][j*4+gate] <- w_hh0[(gate*64+j)*64+k]
    float wi1[64 * 256];   // same regroup of w_ih1
    float wh1[64 * 256];   // same regroup of w_hh1
    float hA[2][64 * 16];  // layer-0 hidden, [buf][k*16 + b]
    float hB[2][64 * 16];  // layer-1 hidden
    float xs[2][BTILE * 4];
};

__device__ __forceinline__ ull pack2(float x, float y) {
    ull r;
    asm("mov.b64 %0, {%1, %2};" : "=l"(r) : "f"(x), "f"(y));
    return r;
}
__device__ __forceinline__ void unpack2(ull v, float& x, float& y) {
    asm("mov.b64 {%0, %1}, %2;" : "=f"(x), "=f"(y) : "l"(v));
}
__device__ __forceinline__ ull fma2(ull a, ull b, ull c) {
    ull d;
    asm("fma.rn.f32x2 %0, %1, %2, %3;" : "=l"(d) : "l"(a), "l"(b), "l"(c));
    return d;
}
__device__ __forceinline__ ull add2(ull a, ull b) {
    ull d;
    asm("add.rn.f32x2 %0, %1, %2;" : "=l"(d) : "l"(a), "l"(b));
    return d;
}
__device__ __forceinline__ float tanh_ap(float x) {
    float y;
    asm("tanh.approx.f32 %0, %1;" : "=f"(y) : "f"(x));
    return y;
}
__device__ __forceinline__ float sig_ap(float x) {
    return fmaf(tanh_ap(x * 0.5f), 0.5f, 0.5f);
}

// acc[g]: gate g packed over 2 batch rows -> 2 cells, c in regs
__device__ __forceinline__ void cell2(const ull acc[4], float c[2], float hn[2]) {
    float i0, i1, f0, f1, g0, g1, o0, o1;
    unpack2(acc[0], i0, i1);
    unpack2(acc[1], f0, f1);
    unpack2(acc[2], g0, g1);
    unpack2(acc[3], o0, o1);
    float I0 = sig_ap(i0), F0 = sig_ap(f0), G0 = tanh_ap(g0), O0 = sig_ap(o0);
    c[0] = F0 * c[0] + I0 * G0;
    hn[0] = O0 * tanh_ap(c[0]);
    float I1 = sig_ap(i1), F1 = sig_ap(f1), G1 = tanh_ap(g1), O1 = sig_ap(o1);
    c[1] = F1 * c[1] + I1 * G1;
    hn[1] = O1 * tanh_ap(c[1]);
}

__global__ void __launch_bounds__(NTHREADS, 1)
lstm_fused_kernel(const float* __restrict__ x,
                  const float* __restrict__ w_ih0, const float* __restrict__ w_hh0,
                  const float* __restrict__ b_ih0, const float* __restrict__ b_hh0,
                  const float* __restrict__ w_ih1, const float* __restrict__ w_hh1,
                  const float* __restrict__ b_ih1, const float* __restrict__ b_hh1,
                  const float* __restrict__ fc_w, const float* __restrict__ fc_b,
                  float* __restrict__ out)
{
    extern __shared__ __align__(16) unsigned char smem_raw[];
    Smem& sh = *reinterpret_cast<Smem*>(smem_raw);
    const int tid = threadIdx.x;
    const int b0 = blockIdx.x * BTILE;

    // ---- stage recurrent weights, regrouped: [k][j*4+gate] ----
    for (int e = tid; e < 64 * 256; e += NTHREADS) {
        int row = e >> 6, k = e & 63;
        int gate = row >> 6, jj = row & 63;
        int d = k * 256 + jj * 4 + gate;
        sh.w0[d] = w_hh0[e];
        sh.wi1[d] = w_ih1[e];
        sh.wh1[d] = w_hh1[e];
    }
    // ---- zero h buffers ----
    for (int e = tid; e < 1024; e += NTHREADS) {
        sh.hA[0][e] = 0.f; sh.hA[1][e] = 0.f;
        sh.hB[0][e] = 0.f; sh.hB[1][e] = 0.f;
    }
    // ---- preload x for t=0 ----
    if (tid < BTILE)
        *(float4*)&sh.xs[0][tid * 4] = ((const float4*)x)[(size_t)(b0 + tid) * TT];

    const int wid = tid >> 5;
    const int lane = tid & 31;
    const int grp = wid >> 3;              // 0=Ga(l0), 1=Gb(l1 rows 0-7), 2=Gc(l1 rows 8-15)
    const int lw = wid & 7;
    const int j = lw * 8 + (lane >> 2);    // hidden unit 0..63
    const int quad = lane & 3;
    const int q4 = quad * 4;               // Ga: rows q4..q4+3
    const int half8 = (grp == 2) ? 8 : 0;  // Gb/Gc batch-half offset
    const int pr2 = half8 + quad * 2;      // Gb/Gc: rows pr2, pr2+1

    float wi0[16], bias0[4];
    ull bias1[4] = {0, 0, 0, 0};
    if (grp == 0) {
#pragma unroll
        for (int g = 0; g < 4; g++) {
            float4 wv = *(const float4*)(w_ih0 + (g * 64 + j) * 4);
            wi0[g * 4 + 0] = wv.x; wi0[g * 4 + 1] = wv.y;
            wi0[g * 4 + 2] = wv.z; wi0[g * 4 + 3] = wv.w;
            bias0[g] = b_ih0[g * 64 + j] + b_hh0[g * 64 + j];
        }
    } else {
#pragma unroll
        for (int g = 0; g < 4; g++) {
            float bb = b_ih1[g * 64 + j] + b_hh1[g * 64 + j];
            bias1[g] = pack2(bb, bb);
        }
    }
    float c[4];
#pragma unroll
    for (int i = 0; i < 4; i++) c[i] = 0.f;

    __syncthreads();

    // ============ pipelined recurrence ============
    // round r: Ga: layer-0 t=r (r<512); Gb/Gc: layer-1 t=r-1 (r>=1), split by batch half
    for (int r = 0; r <= TT; r++) {
        float4 xpre;
        const bool pre = (tid < BTILE) && (r <= TT - 2);
        if (pre) xpre = ((const float4*)x)[(size_t)(b0 + tid) * TT + (r + 1)];

        if (grp == 0) {
            if (r < TT) {
                ull acc[8];  // [g*2+p]: gate g, pair p (rows q4+2p, q4+2p+1)
                const float4* xp = (const float4*)sh.xs[r & 1];
#pragma unroll
                for (int p = 0; p < 2; p++) {
                    float4 xa = xp[(q4 >> 1) + p];  // row pair (q4+2p)/2
                    float4 xb = xp[(q4 >> 1) + p];  // placeholder (fixed below)
                    (void)xb;
                }
                // x projection: rows q4..q4+3
                {
                    float4 xv0 = ((const float4*)sh.xs[r & 1])[q4 + 0];
                    float4 xv1 = ((const float4*)sh.xs[r & 1])[q4 + 1];
                    float4 xv2 = ((const float4*)sh.xs[r & 1])[q4 + 2];
                    float4 xv3 = ((const float4*)sh.xs[r & 1])[q4 + 3];
#pragma unroll
                    for (int g = 0; g < 4; g++) {
                        float s0 = bias0[g] + wi0[g*4]*xv0.x + wi0[g*4+1]*xv0.y
                                            + wi0[g*4+2]*xv0.z + wi0[g*4+3]*xv0.w;
                        float s1 = bias0[g] + wi0[g*4]*xv1.x + wi0[g*4+1]*xv1.y
                                            + wi0[g*4+2]*xv1.z + wi0[g*4+3]*xv1.w;
                        float s2 = bias0[g] + wi0[g*4]*xv2.x + wi0[g*4+1]*xv2.y
                                            + wi0[g*4+2]*xv2.z + wi0[g*4+3]*xv2.w;
                        float s3 = bias0[g] + wi0[g*4]*xv3.x + wi0[g*4+1]*xv3.y
                                            + wi0[g*4+2]*xv3.z + wi0[g*4+3]*xv3.w;
                        acc[g * 2 + 0] = pack2(s0, s1);
                        acc[g * 2 + 1] = pack2(s2, s3);
                    }
                }
                const float* hr = sh.hA[r & 1] + q4;
                const float* wp = sh.w0 + j * 4;
#pragma unroll 8
                for (int k = 0; k < 64; k++) {
                    ulonglong2 hp = *(const ulonglong2*)(hr + k * 16); // rows q4..q4+3
                    float4 w = *(const float4*)(wp + (k << 8));
                    ull wI = pack2(w.x, w.x), wF = pack2(w.y, w.y);
                    ull wG = pack2(w.z, w.z), wO = pack2(w.w, w.w);
                    acc[0] = fma2(hp.x, wI, acc[0]); acc[1] = fma2(hp.y, wI, acc[1]);
                    acc[2] = fma2(hp.x, wF, acc[2]); acc[3] = fma2(hp.y, wF, acc[3]);
                    acc[4] = fma2(hp.x, wG, acc[4]); acc[5] = fma2(hp.y, wG, acc[5]);
                    acc[6] = fma2(hp.x, wO, acc[6]); acc[7] = fma2(hp.y, wO, acc[7]);
                }
                ull g0[4] = { acc[0], acc[2], acc[4], acc[6] };
                ull g1[4] = { acc[1], acc[3], acc[5], acc[7] };
                float hn0[2], hn1[2];
                cell2(g0, c, hn0);
                cell2(g1, c + 2, hn1);
                *(float4*)(sh.hA[(r + 1) & 1] + j * 16 + q4) =
                    make_float4(hn0[0], hn0[1], hn1[0], hn1[1]);
            }
        } else {
            if (r >= 1) {
                ull accA[4], accB[4];  // per-gate, one pair; A = W_ih1*h0, B = W_hh1*h1
#pragma unroll
                for (int g = 0; g < 4; g++) { accA[g] = bias1[g]; accB[g] = 0ull; }
                const float* ha = sh.hA[r & 1] + pr2;
                const float* hb = sh.hB[r & 1] + pr2;
                const float* wia = sh.wi1 + j * 4;
                const float* wib = sh.wh1 + j * 4;
#pragma unroll 8
                for (int k = 0; k < 64; k++) {
                    ull hp0 = *(const ull*)(ha + k * 16);
                    float4 wa = *(const float4*)(wia + (k << 8));
                    accA[0] = fma2(hp0, pack2(wa.x, wa.x), accA[0]);
                    accA[1] = fma2(hp0, pack2(wa.y, wa.y), accA[1]);
                    accA[2] = fma2(hp0, pack2(wa.z, wa.z), accA[2]);
                    accA[3] = fma2(hp0, pack2(wa.w, wa.w), accA[3]);
                    ull hp1 = *(const ull*)(hb + k * 16);
                    float4 wb = *(const float4*)(wib + (k << 8));
                    accB[0] = fma2(hp1, pack2(wb.x, wb.x), accB[0]);
                    accB[1] = fma2(hp1, pack2(wb.y, wb.y), accB[1]);
                    accB[2] = fma2(hp1, pack2(wb.z, wb.z), accB[2]);
                    accB[3] = fma2(hp1, pack2(wb.w, wb.w), accB[3]);
                }
                ull acc[4];
#pragma unroll
                for (int g = 0; g < 4; g++) acc[g] = add2(accA[g], accB[g]);
                float hn[2];
                cell2(acc, c, hn);
                *(ull*)(sh.hB[(r + 1) & 1] + j * 16 + pr2) = pack2(hn[0], hn[1]);
            }
        }

        if (pre) *(float4*)&sh.xs[(r + 1) & 1][tid * 4] = xpre;
        __syncthreads();
    }

    // ============ FC + tanh epilogue ============
    // h_n (layer 1, t=511) finalized in round 512 -> hB[1].
    for (int e = tid; e < 4096; e += NTHREADS) {
        int jj = e >> 6, k = e & 63;
        sh.w0[k * 64 + jj] = fc_w[e]; // transpose: [k][j]
    }
    __syncthreads();

    if (tid < 256) {
        const int q = tid >> 6;  // 4 batch rows each
        const int jo = tid & 63;
        const float* hfin = sh.hB[1];
        float fb = fc_b[jo];
        float acc[4];
#pragma unroll
        for (int m = 0; m < 4; m++) acc[m] = fb;
#pragma unroll 8
        for (int k = 0; k < 64; k++) {
            float w = sh.w0[k * 64 + jo];
#pragma unroll
            for (int m = 0; m < 4; m++)
                acc[m] += w * hfin[k * 16 + q * 4 + m];
        }
#pragma unroll
        for (int m = 0; m < 4; m++)
            out[(size_t)(b0 + q * 4 + m) * 64 + jo] = tanh_ap(acc[m]);
    }
}

extern "C" void kernel_launch(void* const* d_in, const int* in_sizes, int n_in,
                              void* d_out, int out_size) {
    const float* x     = (const float*)d_in[0];
    const float* w_ih0 = (const float*)d_in[1];
    const float* w_hh0 = (const float*)d_in[2];
    const float* b_ih0 = (const float*)d_in[3];
    const float* b_hh0 = (const float*)d_in[4];
    const float* w_ih1 = (const float*)d_in[5];
    const float* w_hh1 = (const float*)d_in[6];
    const float* b_ih1 = (const float*)d_in[7];
    const float* b_hh1 = (const float*)d_in[8];
    const float* fc_w  = (const float*)d_in[9];
    const float* fc_b  = (const float*)d_in[10];
    float* out = (float*)d_out;

    const int smem = (int)sizeof(Smem);
    cudaFuncSetAttribute(lstm_fused_kernel,
                         cudaFuncAttributeMaxDynamicSharedMemorySize, smem);
    lstm_fused_kernel<<<2048 / BTILE, NTHREADS, smem>>>(
        x, w_ih0, w_hh0, b_ih0, b_hh0,
        w_ih1, w_hh1, b_ih1, b_hh1, fc_w, fc_b, out);
}